// round 1
// baseline (speedup 1.0000x reference)
#include <cuda_runtime.h>
#include <cstdint>

typedef unsigned long long u64;

#define KH 3
#define KW 3
#define IN_C 3
#define OUT_C 16
#define QUBITS 5
#define DIM 32
#define FEAT 27
#define EPSV 0.001f
#define IMG 224
#define BATCH 8

// Precomputed circuit matrix rows: g_W[f*16+k] = {Re U[k,f], Re U[k,f], Im U[k,f], Im U[k,f]}
__device__ float4 g_W[FEAT * OUT_C];

// ---------------- packed f32x2 helpers ----------------
__device__ __forceinline__ u64 pack2(float lo, float hi) {
    u64 r; asm("mov.b64 %0, {%1, %2};" : "=l"(r) : "f"(lo), "f"(hi)); return r;
}
__device__ __forceinline__ void unpack2(u64 v, float& lo, float& hi) {
    asm("mov.b64 {%0, %1}, %2;" : "=f"(lo), "=f"(hi) : "l"(v));
}
__device__ __forceinline__ u64 fma2(u64 a, u64 b, u64 c) {
    u64 d; asm("fma.rn.f32x2 %0, %1, %2, %3;" : "=l"(d) : "l"(a), "l"(b), "l"(c)); return d;
}
__device__ __forceinline__ u64 mul2(u64 a, u64 b) {
    u64 d; asm("mul.rn.f32x2 %0, %1, %2;" : "=l"(d) : "l"(a), "l"(b)); return d;
}

// ---------------- setup: build U rows from rotation angles ----------------
// Thread f simulates the circuit applied to basis state e_f -> column f of U.
// Qubit q maps to bit (4-q) of the flattened index.
__global__ void qconv_setup_kernel(const float* __restrict__ w) {
    int f = threadIdx.x;          // 0..31, only f<27 used
    float re[DIM], im[DIM];
#pragma unroll
    for (int i = 0; i < DIM; i++) { re[i] = (i == f) ? 1.0f : 0.0f; im[i] = 0.0f; }

    // Rot(phi,theta,omega) = RZ(omega) RY(theta) RZ(phi) on each qubit
#pragma unroll
    for (int q = 0; q < QUBITS; q++) {
        float phi = w[3 * q + 0], th = w[3 * q + 1], om = w[3 * q + 2];
        float ch = cosf(0.5f * th), sh = sinf(0.5f * th);
        float ap = 0.5f * (phi + om), am = 0.5f * (phi - om);
        float cap = cosf(ap), sap = sinf(ap), cam = cosf(am), sam = sinf(am);
        float u00r =  ch * cap, u00i = -ch * sap;
        float u01r = -sh * cam, u01i = -sh * sam;
        float u10r =  sh * cam, u10i = -sh * sam;
        float u11r =  ch * cap, u11i =  ch * sap;
        const int m = 1 << (4 - q);
#pragma unroll
        for (int i = 0; i < DIM; i++) {
            if (i & m) continue;
            const int j = i | m;
            float r0 = re[i], i0 = im[i], r1 = re[j], i1 = im[j];
            re[i] = u00r * r0 - u00i * i0 + u01r * r1 - u01i * i1;
            im[i] = u00r * i0 + u00i * r0 + u01r * i1 + u01i * r1;
            re[j] = u10r * r0 - u10i * i0 + u11r * r1 - u11i * i1;
            im[j] = u10r * i0 + u10i * r0 + u11r * i1 + u11i * r1;
        }
    }

    // CNOT ring: control q -> target (q+1)%5, applied sequentially
#pragma unroll
    for (int q = 0; q < QUBITS; q++) {
        const int mc = 1 << (4 - q);
        const int mt = 1 << (4 - ((q + 1) % QUBITS));
#pragma unroll
        for (int i = 0; i < DIM; i++) {
            if (!(i & mc) || (i & mt)) continue;
            const int j = i | mt;
            float tr = re[i]; re[i] = re[j]; re[j] = tr;
            float ti = im[i]; im[i] = im[j]; im[j] = ti;
        }
    }

    if (f < FEAT) {
#pragma unroll
        for (int k = 0; k < OUT_C; k++) {
            g_W[f * OUT_C + k] = make_float4(re[k], re[k], im[k], im[k]);
        }
    }
}

// ---------------- main: 2 pixels per thread, packed f32x2 ----------------
// out[b,k,h,w] = 8*(r_k^2 + i_k^2)/||v||^2, r_k = sum_f ReU[k,f]*v_f, v = patch+EPS
__global__ __launch_bounds__(256) void qconv_main_kernel(const float* __restrict__ x,
                                                         float* __restrict__ out) {
    __shared__ ulonglong2 shW[FEAT * OUT_C];   // {(wR,wR),(wI,wI)} per (f,k)
    for (int i = threadIdx.x; i < FEAT * OUT_C; i += 256)
        reinterpret_cast<float4*>(shW)[i] = g_W[i];
    __syncthreads();

    const int t   = blockIdx.x * 256 + threadIdx.x;   // pixel-pair index
    const int w0  = (t % (IMG / 2)) * 2;
    const int row = t / (IMG / 2);
    const int h   = row % IMG;
    const int b   = row / IMG;

    u64 accR[OUT_C], accI[OUT_C], accN = 0ull;
#pragma unroll
    for (int k = 0; k < OUT_C; k++) { accR[k] = 0ull; accI[k] = 0ull; }

    const float* xb = x + (size_t)b * IN_C * IMG * IMG;

#pragma unroll 1
    for (int c = 0; c < IN_C; c++) {
#pragma unroll
        for (int di = 0; di < KH; di++) {
            const int y = h + di - 1;
            const bool ok = ((unsigned)y < (unsigned)IMG);
            const float* rp = xb + ((size_t)c * IMG + y) * IMG + (w0 - 1);
            float tv[4];
            tv[0] = (ok && w0 > 0)         ? __ldg(rp + 0) : 0.0f;
            tv[1] = ok                     ? __ldg(rp + 1) : 0.0f;
            tv[2] = ok                     ? __ldg(rp + 2) : 0.0f;
            tv[3] = (ok && w0 < IMG - 2)   ? __ldg(rp + 3) : 0.0f;
#pragma unroll
            for (int dj = 0; dj < KW; dj++) {
                const u64 v2 = pack2(tv[dj] + EPSV, tv[dj + 1] + EPSV);
                accN = fma2(v2, v2, accN);
                const ulonglong2* wr = &shW[(c * 9 + di * 3 + dj) * OUT_C];
#pragma unroll
                for (int k = 0; k < OUT_C; k++) {
                    const ulonglong2 wq = wr[k];
                    accR[k] = fma2(wq.x, v2, accR[k]);
                    accI[k] = fma2(wq.y, v2, accI[k]);
                }
            }
        }
    }

    float n0, n1;
    unpack2(accN, n0, n1);
    const u64 rn = pack2(__fdividef(8.0f, n0), __fdividef(8.0f, n1));

    float* ob = out + (size_t)b * OUT_C * IMG * IMG + (size_t)h * IMG + w0;
#pragma unroll
    for (int k = 0; k < OUT_C; k++) {
        u64 p = mul2(accI[k], accI[k]);
        p = fma2(accR[k], accR[k], p);
        p = mul2(p, rn);
        *reinterpret_cast<u64*>(ob + (size_t)k * (IMG * IMG)) = p;  // 8B-aligned (w0 even)
    }
}

extern "C" void kernel_launch(void* const* d_in, const int* in_sizes, int n_in,
                              void* d_out, int out_size) {
    const float* x = (const float*)d_in[0];       // (8,3,224,224) float32
    const float* w = (const float*)d_in[1];       // (1,5,3) float32
    float* out = (float*)d_out;                   // (8,16,224,224) float32
    (void)in_sizes; (void)n_in; (void)out_size;

    qconv_setup_kernel<<<1, 32>>>(w);
    const int npairs = BATCH * IMG * (IMG / 2);   // 200704
    qconv_main_kernel<<<npairs / 256, 256>>>(x, out);
}

// round 2
// speedup vs baseline: 1.0086x; 1.0086x over previous
#include <cuda_runtime.h>
#include <cstdint>

typedef unsigned long long u64;

#define KH 3
#define KW 3
#define IN_C 3
#define OUT_C 16
#define QUBITS 5
#define DIM 32
#define FEAT 27
#define EPSV 0.001f
#define IMG 224
#define BATCH 8
#define CG 8            // channels per thread (channel-group size)

// Precomputed circuit matrix rows: g_W[f*16+k] = {Re U[k,f], Re U[k,f], Im U[k,f], Im U[k,f]}
__device__ float4 g_W[FEAT * OUT_C];

// ---------------- packed f32x2 helpers ----------------
__device__ __forceinline__ u64 pack2(float lo, float hi) {
    u64 r; asm("mov.b64 %0, {%1, %2};" : "=l"(r) : "f"(lo), "f"(hi)); return r;
}
__device__ __forceinline__ void unpack2(u64 v, float& lo, float& hi) {
    asm("mov.b64 {%0, %1}, %2;" : "=f"(lo), "=f"(hi) : "l"(v));
}
__device__ __forceinline__ u64 fma2(u64 a, u64 b, u64 c) {
    u64 d; asm("fma.rn.f32x2 %0, %1, %2, %3;" : "=l"(d) : "l"(a), "l"(b), "l"(c)); return d;
}
__device__ __forceinline__ u64 mul2(u64 a, u64 b) {
    u64 d; asm("mul.rn.f32x2 %0, %1, %2;" : "=l"(d) : "l"(a), "l"(b)); return d;
}

// ---------------- setup: build U rows from rotation angles ----------------
__global__ void qconv_setup_kernel(const float* __restrict__ w) {
    int f = threadIdx.x;          // 0..31, only f<27 used
    float re[DIM], im[DIM];
#pragma unroll
    for (int i = 0; i < DIM; i++) { re[i] = (i == f) ? 1.0f : 0.0f; im[i] = 0.0f; }

    // Rot(phi,theta,omega) = RZ(omega) RY(theta) RZ(phi) on each qubit
#pragma unroll
    for (int q = 0; q < QUBITS; q++) {
        float phi = w[3 * q + 0], th = w[3 * q + 1], om = w[3 * q + 2];
        float ch = cosf(0.5f * th), sh = sinf(0.5f * th);
        float ap = 0.5f * (phi + om), am = 0.5f * (phi - om);
        float cap = cosf(ap), sap = sinf(ap), cam = cosf(am), sam = sinf(am);
        float u00r =  ch * cap, u00i = -ch * sap;
        float u01r = -sh * cam, u01i = -sh * sam;
        float u10r =  sh * cam, u10i = -sh * sam;
        float u11r =  ch * cap, u11i =  ch * sap;
        const int m = 1 << (4 - q);
#pragma unroll
        for (int i = 0; i < DIM; i++) {
            if (i & m) continue;
            const int j = i | m;
            float r0 = re[i], i0 = im[i], r1 = re[j], i1 = im[j];
            re[i] = u00r * r0 - u00i * i0 + u01r * r1 - u01i * i1;
            im[i] = u00r * i0 + u00i * r0 + u01r * i1 + u01i * r1;
            re[j] = u10r * r0 - u10i * i0 + u11r * r1 - u11i * i1;
            im[j] = u10r * i0 + u10i * r0 + u11r * i1 + u11i * r1;
        }
    }

    // CNOT ring: control q -> target (q+1)%5
#pragma unroll
    for (int q = 0; q < QUBITS; q++) {
        const int mc = 1 << (4 - q);
        const int mt = 1 << (4 - ((q + 1) % QUBITS));
#pragma unroll
        for (int i = 0; i < DIM; i++) {
            if (!(i & mc) || (i & mt)) continue;
            const int j = i | mt;
            float tr = re[i]; re[i] = re[j]; re[j] = tr;
            float ti = im[i]; im[i] = im[j]; im[j] = ti;
        }
    }

    if (f < FEAT) {
#pragma unroll
        for (int k = 0; k < OUT_C; k++) {
            g_W[f * OUT_C + k] = make_float4(re[k], re[k], im[k], im[k]);
        }
    }
}

// ---------------- main: 2 pixels x 8 channels per thread ----------------
// blockIdx.y selects the channel half. Each thread computes its own norm.
__global__ __launch_bounds__(256, 4) void qconv_main_kernel(const float* __restrict__ x,
                                                            float* __restrict__ out) {
    __shared__ ulonglong2 shW[FEAT * OUT_C];   // {(wR,wR),(wI,wI)} per (f,k)
    for (int i = threadIdx.x; i < FEAT * OUT_C; i += 256)
        reinterpret_cast<float4*>(shW)[i] = g_W[i];
    __syncthreads();

    const int t   = blockIdx.x * 256 + threadIdx.x;   // pixel-pair index
    const int w0  = (t % (IMG / 2)) * 2;
    const int row = t / (IMG / 2);
    const int h   = row % IMG;
    const int b   = row / IMG;
    const int kbase = blockIdx.y * CG;                // channel-group offset

    u64 accR[CG], accI[CG], accN = 0ull;
#pragma unroll
    for (int k = 0; k < CG; k++) { accR[k] = 0ull; accI[k] = 0ull; }

    const float* xb = x + (size_t)b * IN_C * IMG * IMG;
    const ulonglong2* shWg = shW + kbase;

#pragma unroll 1
    for (int c = 0; c < IN_C; c++) {
#pragma unroll
        for (int di = 0; di < KH; di++) {
            const int y = h + di - 1;
            const bool ok = ((unsigned)y < (unsigned)IMG);
            const float* rp = xb + ((size_t)c * IMG + y) * IMG + (w0 - 1);
            float te[4];
            te[0] = ((ok && w0 > 0)       ? __ldg(rp + 0) : 0.0f) + EPSV;
            te[1] = (ok                   ? __ldg(rp + 1) : 0.0f) + EPSV;
            te[2] = (ok                   ? __ldg(rp + 2) : 0.0f) + EPSV;
            te[3] = ((ok && w0 < IMG - 2) ? __ldg(rp + 3) : 0.0f) + EPSV;
#pragma unroll
            for (int dj = 0; dj < KW; dj++) {
                const u64 v2 = pack2(te[dj], te[dj + 1]);
                accN = fma2(v2, v2, accN);
                const ulonglong2* wr = &shWg[(c * 9 + di * 3 + dj) * OUT_C];
#pragma unroll
                for (int k = 0; k < CG; k++) {
                    const ulonglong2 wq = wr[k];
                    accR[k] = fma2(wq.x, v2, accR[k]);
                    accI[k] = fma2(wq.y, v2, accI[k]);
                }
            }
        }
    }

    float n0, n1;
    unpack2(accN, n0, n1);
    const u64 rn = pack2(__fdividef(8.0f, n0), __fdividef(8.0f, n1));

    float* ob = out + (size_t)b * OUT_C * IMG * IMG + (size_t)(kbase) * (IMG * IMG)
              + (size_t)h * IMG + w0;
#pragma unroll
    for (int k = 0; k < CG; k++) {
        u64 p = mul2(accI[k], accI[k]);
        p = fma2(accR[k], accR[k], p);
        p = mul2(p, rn);
        *reinterpret_cast<u64*>(ob + (size_t)k * (IMG * IMG)) = p;  // 8B-aligned (w0 even)
    }
}

extern "C" void kernel_launch(void* const* d_in, const int* in_sizes, int n_in,
                              void* d_out, int out_size) {
    const float* x = (const float*)d_in[0];       // (8,3,224,224) float32
    const float* w = (const float*)d_in[1];       // (1,5,3) float32
    float* out = (float*)d_out;                   // (8,16,224,224) float32
    (void)in_sizes; (void)n_in; (void)out_size;

    qconv_setup_kernel<<<1, 32>>>(w);
    const int npairs = BATCH * IMG * (IMG / 2);   // 200704
    dim3 grid(npairs / 256, OUT_C / CG);          // (784, 2)
    qconv_main_kernel<<<grid, 256>>>(x, out);
}

// round 3
// speedup vs baseline: 1.0334x; 1.0246x over previous
#include <cuda_runtime.h>
#include <cstdint>

typedef unsigned long long u64;

#define KH 3
#define KW 3
#define IN_C 3
#define OUT_C 16
#define QUBITS 5
#define DIM 32
#define FEAT 27
#define EPSV 0.001f
#define IMG 224
#define BATCH 8
#define CG 4            // channels per thread
#define PX 4            // pixels per thread (two f32x2 pairs)

// Precomputed circuit matrix rows: g_W[f*16+k] = {Re U[k,f], Re U[k,f], Im U[k,f], Im U[k,f]}
__device__ float4 g_W[FEAT * OUT_C];

// ---------------- packed f32x2 helpers ----------------
__device__ __forceinline__ u64 pack2(float lo, float hi) {
    u64 r; asm("mov.b64 %0, {%1, %2};" : "=l"(r) : "f"(lo), "f"(hi)); return r;
}
__device__ __forceinline__ void unpack2(u64 v, float& lo, float& hi) {
    asm("mov.b64 {%0, %1}, %2;" : "=f"(lo), "=f"(hi) : "l"(v));
}
__device__ __forceinline__ u64 fma2(u64 a, u64 b, u64 c) {
    u64 d; asm("fma.rn.f32x2 %0, %1, %2, %3;" : "=l"(d) : "l"(a), "l"(b), "l"(c)); return d;
}
__device__ __forceinline__ u64 mul2(u64 a, u64 b) {
    u64 d; asm("mul.rn.f32x2 %0, %1, %2;" : "=l"(d) : "l"(a), "l"(b)); return d;
}

// ---------------- setup: build U rows from rotation angles ----------------
__global__ void qconv_setup_kernel(const float* __restrict__ w) {
    int f = threadIdx.x;          // 0..31, only f<27 used
    float re[DIM], im[DIM];
#pragma unroll
    for (int i = 0; i < DIM; i++) { re[i] = (i == f) ? 1.0f : 0.0f; im[i] = 0.0f; }

    // Rot(phi,theta,omega) = RZ(omega) RY(theta) RZ(phi) on each qubit
#pragma unroll
    for (int q = 0; q < QUBITS; q++) {
        float phi = w[3 * q + 0], th = w[3 * q + 1], om = w[3 * q + 2];
        float ch = cosf(0.5f * th), sh = sinf(0.5f * th);
        float ap = 0.5f * (phi + om), am = 0.5f * (phi - om);
        float cap = cosf(ap), sap = sinf(ap), cam = cosf(am), sam = sinf(am);
        float u00r =  ch * cap, u00i = -ch * sap;
        float u01r = -sh * cam, u01i = -sh * sam;
        float u10r =  sh * cam, u10i = -sh * sam;
        float u11r =  ch * cap, u11i =  ch * sap;
        const int m = 1 << (4 - q);
#pragma unroll
        for (int i = 0; i < DIM; i++) {
            if (i & m) continue;
            const int j = i | m;
            float r0 = re[i], i0 = im[i], r1 = re[j], i1 = im[j];
            re[i] = u00r * r0 - u00i * i0 + u01r * r1 - u01i * i1;
            im[i] = u00r * i0 + u00i * r0 + u01r * i1 + u01i * r1;
            re[j] = u10r * r0 - u10i * i0 + u11r * r1 - u11i * i1;
            im[j] = u10r * i0 + u10i * r0 + u11r * i1 + u11i * r1;
        }
    }

    // CNOT ring: control q -> target (q+1)%5
#pragma unroll
    for (int q = 0; q < QUBITS; q++) {
        const int mc = 1 << (4 - q);
        const int mt = 1 << (4 - ((q + 1) % QUBITS));
#pragma unroll
        for (int i = 0; i < DIM; i++) {
            if (!(i & mc) || (i & mt)) continue;
            const int j = i | mt;
            float tr = re[i]; re[i] = re[j]; re[j] = tr;
            float ti = im[i]; im[i] = im[j]; im[j] = ti;
        }
    }

    if (f < FEAT) {
#pragma unroll
        for (int k = 0; k < OUT_C; k++) {
            g_W[f * OUT_C + k] = make_float4(re[k], re[k], im[k], im[k]);
        }
    }
}

// ---------------- main: 4 pixels x 4 channels per thread ----------------
__global__ __launch_bounds__(256, 4) void qconv_main_kernel(const float* __restrict__ x,
                                                            float* __restrict__ out) {
    __shared__ ulonglong2 shW[FEAT * OUT_C];   // {(wR,wR),(wI,wI)} per (f,k)
    for (int i = threadIdx.x; i < FEAT * OUT_C; i += 256)
        reinterpret_cast<float4*>(shW)[i] = g_W[i];
    __syncthreads();

    const int t   = blockIdx.x * 256 + threadIdx.x;   // pixel-quad index
    const int w0  = (t % (IMG / PX)) * PX;            // multiple of 4
    const int row = t / (IMG / PX);
    const int h   = row % IMG;
    const int b   = row / IMG;
    const int kbase = blockIdx.y * CG;

    u64 accRA[CG], accIA[CG], accRB[CG], accIB[CG];
    u64 nA = 0ull, nB = 0ull;
#pragma unroll
    for (int k = 0; k < CG; k++) { accRA[k] = 0ull; accIA[k] = 0ull; accRB[k] = 0ull; accIB[k] = 0ull; }

    const float* xb = x + (size_t)b * IN_C * IMG * IMG;
    const ulonglong2* shWg = shW + kbase;
    const bool le = (w0 > 0);            // left neighbor exists
    const bool re_ = (w0 < IMG - PX);    // right neighbor exists

#pragma unroll 1
    for (int c = 0; c < IN_C; c++) {
#pragma unroll
        for (int di = 0; di < KH; di++) {
            const int y = h + di - 1;
            const bool ok = ((unsigned)y < (unsigned)IMG);
            const float* rp = xb + ((size_t)c * IMG + y) * IMG + w0;
            float te[PX + 2];
            if (ok) {
                const float4 q = *reinterpret_cast<const float4*>(rp);   // cols w0..w0+3
                te[0] = le  ? __ldg(rp - 1) : 0.0f;
                te[1] = q.x; te[2] = q.y; te[3] = q.z; te[4] = q.w;
                te[5] = re_ ? __ldg(rp + PX) : 0.0f;
            } else {
#pragma unroll
                for (int i = 0; i < PX + 2; i++) te[i] = 0.0f;
            }
#pragma unroll
            for (int i = 0; i < PX + 2; i++) te[i] += EPSV;
#pragma unroll
            for (int dj = 0; dj < KW; dj++) {
                const u64 vA = pack2(te[dj],     te[dj + 1]);   // pixels w0, w0+1
                const u64 vB = pack2(te[dj + 2], te[dj + 3]);   // pixels w0+2, w0+3
                nA = fma2(vA, vA, nA);
                nB = fma2(vB, vB, nB);
                const ulonglong2* wr = &shWg[(c * 9 + di * 3 + dj) * OUT_C];
#pragma unroll
                for (int k = 0; k < CG; k++) {
                    const ulonglong2 wq = wr[k];
                    accRA[k] = fma2(wq.x, vA, accRA[k]);
                    accRB[k] = fma2(wq.x, vB, accRB[k]);
                    accIA[k] = fma2(wq.y, vA, accIA[k]);
                    accIB[k] = fma2(wq.y, vB, accIB[k]);
                }
            }
        }
    }

    float a0, a1, b0, b1;
    unpack2(nA, a0, a1);
    unpack2(nB, b0, b1);
    const u64 rnA = pack2(__fdividef(8.0f, a0), __fdividef(8.0f, a1));
    const u64 rnB = pack2(__fdividef(8.0f, b0), __fdividef(8.0f, b1));

    float* ob = out + (size_t)b * OUT_C * IMG * IMG + (size_t)kbase * (IMG * IMG)
              + (size_t)h * IMG + w0;
#pragma unroll
    for (int k = 0; k < CG; k++) {
        u64 pA = mul2(accIA[k], accIA[k]);
        pA = fma2(accRA[k], accRA[k], pA);
        pA = mul2(pA, rnA);
        u64 pB = mul2(accIB[k], accIB[k]);
        pB = fma2(accRB[k], accRB[k], pB);
        pB = mul2(pB, rnB);
        float4 o;
        unpack2(pA, o.x, o.y);
        unpack2(pB, o.z, o.w);
        *reinterpret_cast<float4*>(ob + (size_t)k * (IMG * IMG)) = o;   // 16B-aligned
    }
}

extern "C" void kernel_launch(void* const* d_in, const int* in_sizes, int n_in,
                              void* d_out, int out_size) {
    const float* x = (const float*)d_in[0];       // (8,3,224,224) float32
    const float* w = (const float*)d_in[1];       // (1,5,3) float32
    float* out = (float*)d_out;                   // (8,16,224,224) float32
    (void)in_sizes; (void)n_in; (void)out_size;

    qconv_setup_kernel<<<1, 32>>>(w);
    const int nquads = BATCH * IMG * (IMG / PX);  // 100352
    dim3 grid(nquads / 256, OUT_C / CG);          // (392, 4)
    qconv_main_kernel<<<grid, 256>>>(x, out);
}

// round 4
// speedup vs baseline: 1.2225x; 1.1830x over previous
#include <cuda_runtime.h>
#include <cstdint>

typedef unsigned long long u64;

#define KH 3
#define KW 3
#define IN_C 3
#define OUT_C 16
#define QUBITS 5
#define DIM 32
#define FEAT 27
#define EPSV 0.001f
#define IMG 224
#define BATCH 8
#define CG 4            // channels per thread
#define PX 4            // pixels per thread

// Precomputed circuit rows: g_W2[f*16+k] = (Re U[k,f], Im U[k,f])
__device__ float2 g_W2[FEAT * OUT_C];

// ---------------- packed f32x2 helpers ----------------
__device__ __forceinline__ u64 pack2(float lo, float hi) {
    u64 r; asm("mov.b64 %0, {%1, %2};" : "=l"(r) : "f"(lo), "f"(hi)); return r;
}
__device__ __forceinline__ void unpack2(u64 v, float& lo, float& hi) {
    asm("mov.b64 {%0, %1}, %2;" : "=f"(lo), "=f"(hi) : "l"(v));
}
__device__ __forceinline__ u64 fma2(u64 a, u64 b, u64 c) {
    u64 d; asm("fma.rn.f32x2 %0, %1, %2, %3;" : "=l"(d) : "l"(a), "l"(b), "l"(c)); return d;
}

// ---------------- setup: build U rows from rotation angles ----------------
__global__ void qconv_setup_kernel(const float* __restrict__ w) {
    int f = threadIdx.x;          // 0..31, only f<27 used
    float re[DIM], im[DIM];
#pragma unroll
    for (int i = 0; i < DIM; i++) { re[i] = (i == f) ? 1.0f : 0.0f; im[i] = 0.0f; }

    // Rot(phi,theta,omega) = RZ(omega) RY(theta) RZ(phi) on each qubit
#pragma unroll
    for (int q = 0; q < QUBITS; q++) {
        float phi = w[3 * q + 0], th = w[3 * q + 1], om = w[3 * q + 2];
        float ch = cosf(0.5f * th), sh = sinf(0.5f * th);
        float ap = 0.5f * (phi + om), am = 0.5f * (phi - om);
        float cap = cosf(ap), sap = sinf(ap), cam = cosf(am), sam = sinf(am);
        float u00r =  ch * cap, u00i = -ch * sap;
        float u01r = -sh * cam, u01i = -sh * sam;
        float u10r =  sh * cam, u10i = -sh * sam;
        float u11r =  ch * cap, u11i =  ch * sap;
        const int m = 1 << (4 - q);
#pragma unroll
        for (int i = 0; i < DIM; i++) {
            if (i & m) continue;
            const int j = i | m;
            float r0 = re[i], i0 = im[i], r1 = re[j], i1 = im[j];
            re[i] = u00r * r0 - u00i * i0 + u01r * r1 - u01i * i1;
            im[i] = u00r * i0 + u00i * r0 + u01r * i1 + u01i * r1;
            re[j] = u10r * r0 - u10i * i0 + u11r * r1 - u11i * i1;
            im[j] = u10r * i0 + u10i * r0 + u11r * i1 + u11i * r1;
        }
    }

    // CNOT ring: control q -> target (q+1)%5
#pragma unroll
    for (int q = 0; q < QUBITS; q++) {
        const int mc = 1 << (4 - q);
        const int mt = 1 << (4 - ((q + 1) % QUBITS));
#pragma unroll
        for (int i = 0; i < DIM; i++) {
            if (!(i & mc) || (i & mt)) continue;
            const int j = i | mt;
            float tr = re[i]; re[i] = re[j]; re[j] = tr;
            float ti = im[i]; im[i] = im[j]; im[j] = ti;
        }
    }

    if (f < FEAT) {
#pragma unroll
        for (int k = 0; k < OUT_C; k++) {
            g_W2[f * OUT_C + k] = make_float2(re[k], im[k]);
        }
    }
}

// ---------------- main: 4 pixels x 4 channels, (Re,Im)-packed accumulators ----------------
__global__ __launch_bounds__(256, 4) void qconv_main_kernel(const float* __restrict__ x,
                                                            float* __restrict__ out) {
    __shared__ u64 shW[FEAT * OUT_C];   // (wR, wI) per (f,k), 8B each
    for (int i = threadIdx.x; i < FEAT * OUT_C; i += 256)
        reinterpret_cast<float2*>(shW)[i] = g_W2[i];
    __syncthreads();

    const int t   = blockIdx.x * 256 + threadIdx.x;   // pixel-quad index
    const int w0  = (t % (IMG / PX)) * PX;            // multiple of 4
    const int row = t / (IMG / PX);
    const int h   = row % IMG;
    const int b   = row / IMG;
    const int kbase = blockIdx.y * CG;

    u64 acc[PX][CG];
#pragma unroll
    for (int p = 0; p < PX; p++)
#pragma unroll
        for (int k = 0; k < CG; k++) acc[p][k] = 0ull;
    float S[PX + 2];                                  // per-column square sums
#pragma unroll
    for (int i = 0; i < PX + 2; i++) S[i] = 0.0f;

    const float* xb = x + (size_t)b * IN_C * IMG * IMG;
    const u64* shWg = shW + kbase;
    const bool le  = (w0 > 0);
    const bool re_ = (w0 < IMG - PX);

#pragma unroll 1
    for (int c = 0; c < IN_C; c++) {
#pragma unroll
        for (int di = 0; di < KH; di++) {
            const int y = h + di - 1;
            const bool ok = ((unsigned)y < (unsigned)IMG);
            const float* rp = xb + ((size_t)c * IMG + y) * IMG + w0;
            float te[PX + 2];
            if (ok) {
                const float4 q = *reinterpret_cast<const float4*>(rp);
                te[0] = le  ? __ldg(rp - 1) : 0.0f;
                te[1] = q.x; te[2] = q.y; te[3] = q.z; te[4] = q.w;
                te[5] = re_ ? __ldg(rp + PX) : 0.0f;
            } else {
#pragma unroll
                for (int i = 0; i < PX + 2; i++) te[i] = 0.0f;
            }
            u64 dup[PX + 2];
#pragma unroll
            for (int i = 0; i < PX + 2; i++) {
                te[i] += EPSV;
                S[i] = fmaf(te[i], te[i], S[i]);
                dup[i] = pack2(te[i], te[i]);
            }
#pragma unroll
            for (int dj = 0; dj < KW; dj++) {
                const u64* wr = &shWg[(c * 9 + di * 3 + dj) * OUT_C];
                const ulonglong2 w01 = *reinterpret_cast<const ulonglong2*>(&wr[0]);
                const ulonglong2 w23 = *reinterpret_cast<const ulonglong2*>(&wr[2]);
#pragma unroll
                for (int p = 0; p < PX; p++) {
                    const u64 vv = dup[p + dj];
                    acc[p][0] = fma2(w01.x, vv, acc[p][0]);
                    acc[p][1] = fma2(w01.y, vv, acc[p][1]);
                    acc[p][2] = fma2(w23.x, vv, acc[p][2]);
                    acc[p][3] = fma2(w23.y, vv, acc[p][3]);
                }
            }
        }
    }

    float rn[PX];
#pragma unroll
    for (int p = 0; p < PX; p++)
        rn[p] = __fdividef(8.0f, S[p] + S[p + 1] + S[p + 2]);

    float* ob = out + (size_t)b * OUT_C * IMG * IMG + (size_t)kbase * (IMG * IMG)
              + (size_t)h * IMG + w0;
#pragma unroll
    for (int k = 0; k < CG; k++) {
        float4 o;
        float* ov = reinterpret_cast<float*>(&o);
#pragma unroll
        for (int p = 0; p < PX; p++) {
            float R, I;
            unpack2(acc[p][k], R, I);
            ov[p] = fmaf(R, R, I * I) * rn[p];
        }
        *reinterpret_cast<float4*>(ob + (size_t)k * (IMG * IMG)) = o;   // 16B-aligned
    }
}

extern "C" void kernel_launch(void* const* d_in, const int* in_sizes, int n_in,
                              void* d_out, int out_size) {
    const float* x = (const float*)d_in[0];       // (8,3,224,224) float32
    const float* w = (const float*)d_in[1];       // (1,5,3) float32
    float* out = (float*)d_out;                   // (8,16,224,224) float32
    (void)in_sizes; (void)n_in; (void)out_size;

    qconv_setup_kernel<<<1, 32>>>(w);
    const int nquads = BATCH * IMG * (IMG / PX);  // 100352
    dim3 grid(nquads / 256, OUT_C / CG);          // (392, 4)
    qconv_main_kernel<<<grid, 256>>>(x, out);
}